// round 4
// baseline (speedup 1.0000x reference)
#include <cuda_runtime.h>
#include <cuda_bf16.h>
#include <math.h>

#define Nn 50000
#define Ee 800000
#define Cc 128
#define EPS_COS 1e-8f
#define EPS_EUD 1e-6f

// ------------------- scratch (device globals; no allocs allowed) -------------
__device__ float g_deg[Nn];
__device__ float g_nrm[Nn];
__device__ float g_ecos[Ee];
__device__ float g_eeud[Ee];
__device__ float g_aggA[Nn * Cc];
__device__ float g_aggB[Nn * Cc];
__device__ float g_xW[Nn * Cc];
__device__ float g_xW2[Nn * Cc];
__device__ float g_x1[Nn * Cc];
__device__ float g_x2[Nn * Cc];
__device__ float g_beta[Nn * 4];

// ----------------------------- kernels --------------------------------------

__global__ void zero_kernel(float* __restrict__ p, int n) {
    int i = blockIdx.x * blockDim.x + threadIdx.x;
    if (i < n) p[i] = 0.f;
}

// one warp per node: L2 norm of each 128-float row
__global__ void node_norm_kernel(const float* __restrict__ x, float* __restrict__ nrm) {
    int node = (blockIdx.x * blockDim.x + threadIdx.x) >> 5;
    int lane = threadIdx.x & 31;
    if (node >= Nn) return;
    float4 v = reinterpret_cast<const float4*>(x + (size_t)node * Cc)[lane];
    float s = v.x * v.x + v.y * v.y + v.z * v.z + v.w * v.w;
    #pragma unroll
    for (int o = 16; o; o >>= 1) s += __shfl_xor_sync(0xffffffffu, s, o);
    if (lane == 0) nrm[node] = sqrtf(s);
}

// one warp per edge: cosine sim + euclidean distance on x, plus degree count
__global__ void edge_sim1_kernel(const int* __restrict__ row, const int* __restrict__ col,
                                 const float* __restrict__ x, const float* __restrict__ nrm,
                                 float* __restrict__ ecos, float* __restrict__ eeud,
                                 float* __restrict__ deg) {
    int e = (blockIdx.x * blockDim.x + threadIdx.x) >> 5;
    int lane = threadIdx.x & 31;
    if (e >= Ee) return;
    int r = __ldg(row + e), c = __ldg(col + e);
    float4 a = reinterpret_cast<const float4*>(x + (size_t)r * Cc)[lane];
    float4 b = reinterpret_cast<const float4*>(x + (size_t)c * Cc)[lane];
    float dot = a.x * b.x + a.y * b.y + a.z * b.z + a.w * b.w;
    float dx = a.x - b.x + EPS_EUD, dy = a.y - b.y + EPS_EUD;
    float dz = a.z - b.z + EPS_EUD, dw = a.w - b.w + EPS_EUD;
    float d2 = dx * dx + dy * dy + dz * dz + dw * dw;
    #pragma unroll
    for (int o = 16; o; o >>= 1) {
        dot += __shfl_xor_sync(0xffffffffu, dot, o);
        d2  += __shfl_xor_sync(0xffffffffu, d2, o);
    }
    if (lane == 0) {
        ecos[e] = dot / fmaxf(nrm[r] * nrm[c], EPS_COS);
        eeud[e] = sqrtf(d2);
        atomicAdd(&deg[r], 1.0f);
    }
}

// one warp per edge: cos on x3, eud on x4
__global__ void edge_sim2_kernel(const int* __restrict__ row, const int* __restrict__ col,
                                 const float* __restrict__ x3, const float* __restrict__ x4,
                                 const float* __restrict__ nrm3,
                                 float* __restrict__ ecos, float* __restrict__ eeud) {
    int e = (blockIdx.x * blockDim.x + threadIdx.x) >> 5;
    int lane = threadIdx.x & 31;
    if (e >= Ee) return;
    int r = __ldg(row + e), c = __ldg(col + e);
    float4 a3 = reinterpret_cast<const float4*>(x3 + (size_t)r * Cc)[lane];
    float4 b3 = reinterpret_cast<const float4*>(x3 + (size_t)c * Cc)[lane];
    float dot = a3.x * b3.x + a3.y * b3.y + a3.z * b3.z + a3.w * b3.w;
    float4 a4 = reinterpret_cast<const float4*>(x4 + (size_t)r * Cc)[lane];
    float4 b4 = reinterpret_cast<const float4*>(x4 + (size_t)c * Cc)[lane];
    float dx = a4.x - b4.x + EPS_EUD, dy = a4.y - b4.y + EPS_EUD;
    float dz = a4.z - b4.z + EPS_EUD, dw = a4.w - b4.w + EPS_EUD;
    float d2 = dx * dx + dy * dy + dz * dz + dw * dw;
    #pragma unroll
    for (int o = 16; o; o >>= 1) {
        dot += __shfl_xor_sync(0xffffffffu, dot, o);
        d2  += __shfl_xor_sync(0xffffffffu, d2, o);
    }
    if (lane == 0) {
        ecos[e] = dot / fmaxf(nrm3[r] * nrm3[c], EPS_COS);
        eeud[e] = sqrtf(d2);
    }
}

// layer0 scatter: both branches read the same x[col] row
__global__ void scatter_l0_kernel(const int* __restrict__ row, const int* __restrict__ col,
                                  const float* __restrict__ x,
                                  const float* __restrict__ wA, const float* __restrict__ wB,
                                  float* __restrict__ aggA, float* __restrict__ aggB) {
    int e = (blockIdx.x * blockDim.x + threadIdx.x) >> 5;
    int lane = threadIdx.x & 31;
    if (e >= Ee) return;
    int r = __ldg(row + e), c = __ldg(col + e);
    float wa = __ldg(wA + e), wb = __ldg(wB + e);
    float4 v = reinterpret_cast<const float4*>(x + (size_t)c * Cc)[lane];
    float* dA = aggA + (size_t)r * Cc + lane * 4;
    atomicAdd(dA + 0, wa * v.x); atomicAdd(dA + 1, wa * v.y);
    atomicAdd(dA + 2, wa * v.z); atomicAdd(dA + 3, wa * v.w);
    float* dB = aggB + (size_t)r * Cc + lane * 4;
    atomicAdd(dB + 0, wb * v.x); atomicAdd(dB + 1, wb * v.y);
    atomicAdd(dB + 2, wb * v.z); atomicAdd(dB + 3, wb * v.w);
}

// layer1 scatter: branch A uses x3, branch B uses x4
__global__ void scatter_l1_kernel(const int* __restrict__ row, const int* __restrict__ col,
                                  const float* __restrict__ fA, const float* __restrict__ fB,
                                  const float* __restrict__ wA, const float* __restrict__ wB,
                                  float* __restrict__ aggA, float* __restrict__ aggB) {
    int e = (blockIdx.x * blockDim.x + threadIdx.x) >> 5;
    int lane = threadIdx.x & 31;
    if (e >= Ee) return;
    int r = __ldg(row + e), c = __ldg(col + e);
    float wa = __ldg(wA + e), wb = __ldg(wB + e);
    float4 va = reinterpret_cast<const float4*>(fA + (size_t)c * Cc)[lane];
    float4 vb = reinterpret_cast<const float4*>(fB + (size_t)c * Cc)[lane];
    float* dA = aggA + (size_t)r * Cc + lane * 4;
    atomicAdd(dA + 0, wa * va.x); atomicAdd(dA + 1, wa * va.y);
    atomicAdd(dA + 2, wa * va.z); atomicAdd(dA + 3, wa * va.w);
    float* dB = aggB + (size_t)r * Cc + lane * 4;
    atomicAdd(dB + 0, wb * vb.x); atomicAdd(dB + 1, wb * vb.y);
    atomicAdd(dB + 2, wb * vb.z); atomicAdd(dB + 3, wb * vb.w);
}

// divide both aggs by max(deg, 1)
__global__ void finalize_agg_kernel(float* __restrict__ aggA, float* __restrict__ aggB,
                                    const float* __restrict__ deg) {
    int i = blockIdx.x * blockDim.x + threadIdx.x;
    if (i >= Nn * Cc) return;
    float d = 1.0f / fmaxf(deg[i >> 7], 1.0f);
    aggA[i] *= d;
    aggB[i] *= d;
}

// Cout[nrows,128] = maybe_relu(A @ W + D + bias); W is 128x128 in smem
__global__ void gemm128_kernel(const float* __restrict__ A, const float* __restrict__ W,
                               const float* __restrict__ D, const float* __restrict__ bias,
                               float* __restrict__ Cout, int nrows, int relu) {
    extern __shared__ float sm[];
    float* Ws = sm;            // 128*128
    float* As = sm + Cc * Cc;  // 32*128
    int t = threadIdx.x;       // 128 threads; t = output column
    #pragma unroll 8
    for (int k = 0; k < Cc; k++) Ws[k * Cc + t] = W[k * Cc + t];
    int row0 = blockIdx.x * 32;
    #pragma unroll 8
    for (int r = 0; r < 32; r++) {
        int rr = row0 + r;
        As[r * Cc + t] = (rr < nrows) ? A[(size_t)rr * Cc + t] : 0.f;
    }
    __syncthreads();
    float bv = bias ? bias[t] : 0.f;
    for (int r0 = 0; r0 < 32; r0 += 4) {
        float a0 = 0.f, a1 = 0.f, a2 = 0.f, a3 = 0.f;
        #pragma unroll
        for (int k = 0; k < Cc; k++) {
            float w = Ws[k * Cc + t];
            a0 += As[(r0 + 0) * Cc + k] * w;
            a1 += As[(r0 + 1) * Cc + k] * w;
            a2 += As[(r0 + 2) * Cc + k] * w;
            a3 += As[(r0 + 3) * Cc + k] * w;
        }
        float accs[4] = {a0, a1, a2, a3};
        #pragma unroll
        for (int i = 0; i < 4; i++) {
            int rr = row0 + r0 + i;
            if (rr < nrows) {
                float v = accs[i] + bv + (D ? D[(size_t)rr * Cc + t] : 0.f);
                Cout[(size_t)rr * Cc + t] = relu ? fmaxf(v, 0.f) : v;
            }
        }
    }
}

// attention scores + softmax -> beta[n][4]. 256 threads = 4 branches x 64 hidden.
__global__ void attn_kernel(const float* __restrict__ x1, const float* __restrict__ x2,
                            const float* __restrict__ x3, const float* __restrict__ x4,
                            const float* __restrict__ W1, const float* __restrict__ b1,
                            const float* __restrict__ W2, float* __restrict__ beta) {
    __shared__ float W1s[Cc * 64];  // 32KB, [c][h]
    __shared__ float zs[4 * Cc];
    __shared__ float wred[8];
    int t = threadIdx.x;            // 0..255
    int k = t >> 6;                 // branch 0..3
    int h = t & 63;                 // hidden unit
    for (int i = t; i < Cc * 64; i += 256) W1s[i] = W1[i];
    float b1h = b1[h];
    float W2h = W2[h];
    for (int n = blockIdx.x; n < Nn; n += gridDim.x) {
        __syncthreads();  // protect zs/wred from previous iteration readers
        {
            int c0 = t & 127;
            size_t off = (size_t)n * Cc + c0;
            // i = t covers branches 0,1 ; i = t+256 covers branches 2,3
            zs[t]       = (t < 128) ? x1[off] : x2[off];
            zs[t + 256] = (t < 128) ? x3[off] : x4[off];
        }
        __syncthreads();
        float acc = b1h;
        #pragma unroll 4
        for (int c = 0; c < Cc; c++) acc += zs[k * Cc + c] * W1s[c * 64 + h];
        float v = tanhf(acc) * W2h;
        #pragma unroll
        for (int o = 16; o; o >>= 1) v += __shfl_xor_sync(0xffffffffu, v, o);
        if ((t & 31) == 0) wred[t >> 5] = v;
        __syncthreads();
        if (t == 0) {
            float w0 = wred[0] + wred[1];
            float w1v = wred[2] + wred[3];
            float w2v = wred[4] + wred[5];
            float w3v = wred[6] + wred[7];
            float m = fmaxf(fmaxf(w0, w1v), fmaxf(w2v, w3v));
            float e0 = __expf(w0 - m), e1 = __expf(w1v - m);
            float e2 = __expf(w2v - m), e3 = __expf(w3v - m);
            float inv = 1.0f / (e0 + e1 + e2 + e3);
            beta[n * 4 + 0] = e0 * inv;
            beta[n * 4 + 1] = e1 * inv;
            beta[n * 4 + 2] = e2 * inv;
            beta[n * 4 + 3] = e3 * inv;
        }
    }
}

__global__ void emb_kernel(const float* __restrict__ beta,
                           const float* __restrict__ x1, const float* __restrict__ x2,
                           const float* __restrict__ x3, const float* __restrict__ x4,
                           float* __restrict__ out) {
    int i = blockIdx.x * blockDim.x + threadIdx.x;
    if (i >= Nn * Cc) return;
    const float* bb = beta + (size_t)(i >> 7) * 4;
    out[i] = bb[0] * x1[i] + bb[1] * x2[i] + bb[2] * x3[i] + bb[3] * x4[i];
}

// ----------------------------- launcher --------------------------------------

extern "C" void kernel_launch(void* const* d_in, const int* in_sizes, int n_in,
                              void* d_out, int out_size) {
    const float* x    = (const float*)d_in[0];
    const int*   row  = (const int*)d_in[1];
    const int*   col  = (const int*)d_in[2];
    const float* Wl0  = (const float*)d_in[3];
    const float* bl0  = (const float*)d_in[4];
    const float* Wr0  = (const float*)d_in[5];
    const float* Wl1  = (const float*)d_in[6];
    const float* bl1  = (const float*)d_in[7];
    const float* Wr1  = (const float*)d_in[8];
    const float* aW1  = (const float*)d_in[9];
    const float* ab1  = (const float*)d_in[10];
    const float* aW2  = (const float*)d_in[11];

    float* out = (float*)d_out;
    float* emb = out;
    float* x3  = out + (size_t)Nn * Cc;
    float* x4  = out + (size_t)2 * Nn * Cc;

    float *p_deg, *p_nrm, *p_ecos, *p_eeud, *p_aggA, *p_aggB, *p_xW, *p_xW2, *p_x1, *p_x2, *p_beta;
    cudaGetSymbolAddress((void**)&p_deg, g_deg);
    cudaGetSymbolAddress((void**)&p_nrm, g_nrm);
    cudaGetSymbolAddress((void**)&p_ecos, g_ecos);
    cudaGetSymbolAddress((void**)&p_eeud, g_eeud);
    cudaGetSymbolAddress((void**)&p_aggA, g_aggA);
    cudaGetSymbolAddress((void**)&p_aggB, g_aggB);
    cudaGetSymbolAddress((void**)&p_xW, g_xW);
    cudaGetSymbolAddress((void**)&p_xW2, g_xW2);
    cudaGetSymbolAddress((void**)&p_x1, g_x1);
    cudaGetSymbolAddress((void**)&p_x2, g_x2);
    cudaGetSymbolAddress((void**)&p_beta, g_beta);

    const int NC = Nn * Cc;
    const int gemm_smem = (Cc * Cc + 32 * Cc) * (int)sizeof(float);  // 81920
    cudaFuncSetAttribute(gemm128_kernel, cudaFuncAttributeMaxDynamicSharedMemorySize, gemm_smem);

    const int ZB = 256;
    const int sim_blocks  = (Ee * 32) / 256;       // 100000
    const int norm_blocks = (Nn * 32 + 255) / 256; // 6250
    const int ew_blocks   = (NC + ZB - 1) / ZB;    // 25000
    const int gemm_blocks = (Nn + 31) / 32;        // 1563

    // ---- layer 0 ----
    zero_kernel<<<(Nn + ZB - 1) / ZB, ZB>>>(p_deg, Nn);
    zero_kernel<<<ew_blocks, ZB>>>(p_aggA, NC);
    zero_kernel<<<ew_blocks, ZB>>>(p_aggB, NC);
    node_norm_kernel<<<norm_blocks, 256>>>(x, p_nrm);
    edge_sim1_kernel<<<sim_blocks, 256>>>(row, col, x, p_nrm, p_ecos, p_eeud, p_deg);
    scatter_l0_kernel<<<sim_blocks, 256>>>(row, col, x, p_ecos, p_eeud, p_aggA, p_aggB);
    finalize_agg_kernel<<<ew_blocks, ZB>>>(p_aggA, p_aggB, p_deg);

    gemm128_kernel<<<gemm_blocks, 128, gemm_smem>>>(x, Wr0, nullptr, nullptr, p_xW, Nn, 0);
    gemm128_kernel<<<gemm_blocks, 128, gemm_smem>>>(p_aggA, Wl0, p_xW, bl0, x3, Nn, 1);
    gemm128_kernel<<<gemm_blocks, 128, gemm_smem>>>(p_aggB, Wl0, p_xW, bl0, x4, Nn, 1);

    // ---- layer 1 ----
    node_norm_kernel<<<norm_blocks, 256>>>(x3, p_nrm);
    edge_sim2_kernel<<<sim_blocks, 256>>>(row, col, x3, x4, p_nrm, p_ecos, p_eeud);
    zero_kernel<<<ew_blocks, ZB>>>(p_aggA, NC);
    zero_kernel<<<ew_blocks, ZB>>>(p_aggB, NC);
    scatter_l1_kernel<<<sim_blocks, 256>>>(row, col, x3, x4, p_ecos, p_eeud, p_aggA, p_aggB);
    finalize_agg_kernel<<<ew_blocks, ZB>>>(p_aggA, p_aggB, p_deg);

    gemm128_kernel<<<gemm_blocks, 128, gemm_smem>>>(x3, Wr1, nullptr, nullptr, p_xW, Nn, 0);
    gemm128_kernel<<<gemm_blocks, 128, gemm_smem>>>(x4, Wr1, nullptr, nullptr, p_xW2, Nn, 0);
    gemm128_kernel<<<gemm_blocks, 128, gemm_smem>>>(p_aggA, Wl1, p_xW, bl1, p_x1, Nn, 0);
    gemm128_kernel<<<gemm_blocks, 128, gemm_smem>>>(p_aggB, Wl1, p_xW2, bl1, p_x2, Nn, 0);

    // ---- attention pooling ----
    attn_kernel<<<1184, 256>>>(p_x1, p_x2, x3, x4, aW1, ab1, aW2, p_beta);
    emb_kernel<<<ew_blocks, ZB>>>(p_beta, p_x1, p_x2, x3, x4, emb);
}

// round 9
// speedup vs baseline: 2.5900x; 2.5900x over previous
#include <cuda_runtime.h>
#include <cuda_bf16.h>
#include <math.h>

#define Nn 50000
#define Ee 800000
#define Cc 128
#define EPS_COS 1e-8f
#define EPS_EUD 1e-6f

// ---------------- f32x2 packed-math macros (ptxas won't auto-fuse) ----------
#define PACKD(d, a)   asm("mov.b64 %0, {%1, %1};" : "=l"(d) : "r"(__float_as_int(a)))
#define PACK2(d, a, b) asm("mov.b64 %0, {%1, %2};" : "=l"(d) : "r"(__float_as_int(a)), "r"(__float_as_int(b)))
#define FMA2(acc, a, b) asm("fma.rn.f32x2 %0, %1, %2, %0;" : "+l"(acc) : "l"(a), "l"(b))
#define UNPK(lo, hi, v) do { unsigned int _u0, _u1; \
    asm("mov.b64 {%0, %1}, %2;" : "=r"(_u0), "=r"(_u1) : "l"(v)); \
    lo = __int_as_float(_u0); hi = __int_as_float(_u1); } while (0)

// ------------------- scratch (device globals; no allocs allowed) -------------
__device__ int   g_cnt[Nn];
__device__ int   g_cursor[Nn];
__device__ int   g_rowstart[Nn + 1];
__device__ int   g_ecol[Ee];
__device__ float g_nrm[Nn];
__device__ float g_aggA[Nn * Cc];
__device__ float g_aggB[Nn * Cc];
__device__ float g_xW[Nn * Cc];
__device__ float g_xW2[Nn * Cc];
__device__ float g_x1[Nn * Cc];
__device__ float g_x2[Nn * Cc];

// ----------------------------- kernels --------------------------------------

__global__ void zero_int_kernel(int* __restrict__ p, int n) {
    int i = blockIdx.x * blockDim.x + threadIdx.x;
    if (i < n) p[i] = 0;
}

// one warp per node: L2 norm of each 128-float row (input x only)
__global__ void node_norm_kernel(const float* __restrict__ x, float* __restrict__ nrm) {
    int node = (blockIdx.x * blockDim.x + threadIdx.x) >> 5;
    int lane = threadIdx.x & 31;
    if (node >= Nn) return;
    float4 v = reinterpret_cast<const float4*>(x + (size_t)node * Cc)[lane];
    float s = v.x * v.x + v.y * v.y + v.z * v.z + v.w * v.w;
    #pragma unroll
    for (int o = 16; o; o >>= 1) s += __shfl_xor_sync(0xffffffffu, s, o);
    if (lane == 0) nrm[node] = sqrtf(s);
}

__global__ void count_kernel(const int* __restrict__ row, int* __restrict__ cnt) {
    int e = blockIdx.x * blockDim.x + threadIdx.x;
    if (e < Ee) atomicAdd(&cnt[row[e]], 1);
}

// single block, 1024 threads: exclusive scan of cnt -> row_start & cursor
__global__ void scan_kernel(const int* __restrict__ cnt, int* __restrict__ row_start,
                            int* __restrict__ cursor) {
    __shared__ int wsum[32];
    __shared__ int run;
    int t = threadIdx.x, lane = t & 31, w = t >> 5;
    if (t == 0) run = 0;
    __syncthreads();
    for (int base = 0; base < Nn; base += 1024) {
        int i = base + t;
        int v = (i < Nn) ? cnt[i] : 0;
        int xx = v;
        #pragma unroll
        for (int o = 1; o < 32; o <<= 1) {
            int y = __shfl_up_sync(0xffffffffu, xx, o);
            if (lane >= o) xx += y;
        }
        if (lane == 31) wsum[w] = xx;
        __syncthreads();
        if (w == 0) {
            int s = wsum[lane];
            #pragma unroll
            for (int o = 1; o < 32; o <<= 1) {
                int y = __shfl_up_sync(0xffffffffu, s, o);
                if (lane >= o) s += y;
            }
            wsum[lane] = s;
        }
        __syncthreads();
        int excl = run + (w ? wsum[w - 1] : 0) + xx - v;
        if (i < Nn) { row_start[i] = excl; cursor[i] = excl; }
        __syncthreads();
        if (t == 0) run += wsum[31];
        __syncthreads();
    }
    if (threadIdx.x == 0) row_start[Nn] = run;
}

// thread per edge: CSR column fill only (weights computed inline in gathers)
__global__ void fill_kernel(const int* __restrict__ row, const int* __restrict__ col,
                            int* __restrict__ cursor, int* __restrict__ ecol) {
    int e = blockIdx.x * blockDim.x + threadIdx.x;
    if (e >= Ee) return;
    int r = __ldg(row + e);
    int pos = atomicAdd(&cursor[r], 1);
    ecol[pos] = __ldg(col + e);
}

// warp per node, layer 0: inline cos+eud weights from x, dual accumulate.
__global__ void gather_fused0_kernel(const int* __restrict__ rs, const int* __restrict__ ecol,
                                     const float* __restrict__ x, const float* __restrict__ nrm,
                                     float* __restrict__ aggA, float* __restrict__ aggB) {
    int n = (blockIdx.x * blockDim.x + threadIdx.x) >> 5;
    int lane = threadIdx.x & 31;
    if (n >= Nn) return;
    int s = rs[n], e = rs[n + 1];
    float4 xn = reinterpret_cast<const float4*>(x)[(size_t)n * 32 + lane];
    float nn = nrm[n];
    float4 aA = make_float4(0.f, 0.f, 0.f, 0.f);
    float4 aB = make_float4(0.f, 0.f, 0.f, 0.f);
    #pragma unroll 2
    for (int j = s; j < e; j++) {
        int c = __ldg(ecol + j);
        float4 v = reinterpret_cast<const float4*>(x)[(size_t)c * 32 + lane];
        float dot = xn.x * v.x + xn.y * v.y + xn.z * v.z + xn.w * v.w;
        float dx = xn.x - v.x + EPS_EUD, dy = xn.y - v.y + EPS_EUD;
        float dz = xn.z - v.z + EPS_EUD, dw = xn.w - v.w + EPS_EUD;
        float d2 = dx * dx + dy * dy + dz * dz + dw * dw;
        #pragma unroll
        for (int o = 16; o; o >>= 1) {
            dot += __shfl_xor_sync(0xffffffffu, dot, o);
            d2  += __shfl_xor_sync(0xffffffffu, d2, o);
        }
        float wa = dot / fmaxf(nn * __ldg(nrm + c), EPS_COS);
        float wb = sqrtf(d2);
        aA.x += wa * v.x; aA.y += wa * v.y; aA.z += wa * v.z; aA.w += wa * v.w;
        aB.x += wb * v.x; aB.y += wb * v.y; aB.z += wb * v.z; aB.w += wb * v.w;
    }
    float inv = 1.f / fmaxf((float)(e - s), 1.f);
    aA.x *= inv; aA.y *= inv; aA.z *= inv; aA.w *= inv;
    aB.x *= inv; aB.y *= inv; aB.z *= inv; aB.w *= inv;
    reinterpret_cast<float4*>(aggA)[(size_t)n * 32 + lane] = aA;
    reinterpret_cast<float4*>(aggB)[(size_t)n * 32 + lane] = aB;
}

// warp per node, layer 1: cos on x3 (-> aggA from x3), eud on x4 (-> aggB from x4).
__global__ void gather_fused1_kernel(const int* __restrict__ rs, const int* __restrict__ ecol,
                                     const float* __restrict__ x3, const float* __restrict__ x4,
                                     const float* __restrict__ nrm3,
                                     float* __restrict__ aggA, float* __restrict__ aggB) {
    int n = (blockIdx.x * blockDim.x + threadIdx.x) >> 5;
    int lane = threadIdx.x & 31;
    if (n >= Nn) return;
    int s = rs[n], e = rs[n + 1];
    float4 an = reinterpret_cast<const float4*>(x3)[(size_t)n * 32 + lane];
    float4 bn = reinterpret_cast<const float4*>(x4)[(size_t)n * 32 + lane];
    float nn = nrm3[n];
    float4 aA = make_float4(0.f, 0.f, 0.f, 0.f);
    float4 aB = make_float4(0.f, 0.f, 0.f, 0.f);
    #pragma unroll 2
    for (int j = s; j < e; j++) {
        int c = __ldg(ecol + j);
        float4 va = reinterpret_cast<const float4*>(x3)[(size_t)c * 32 + lane];
        float4 vb = reinterpret_cast<const float4*>(x4)[(size_t)c * 32 + lane];
        float dot = an.x * va.x + an.y * va.y + an.z * va.z + an.w * va.w;
        float dx = bn.x - vb.x + EPS_EUD, dy = bn.y - vb.y + EPS_EUD;
        float dz = bn.z - vb.z + EPS_EUD, dw = bn.w - vb.w + EPS_EUD;
        float d2 = dx * dx + dy * dy + dz * dz + dw * dw;
        #pragma unroll
        for (int o = 16; o; o >>= 1) {
            dot += __shfl_xor_sync(0xffffffffu, dot, o);
            d2  += __shfl_xor_sync(0xffffffffu, d2, o);
        }
        float wa = dot / fmaxf(nn * __ldg(nrm3 + c), EPS_COS);
        float wb = sqrtf(d2);
        aA.x += wa * va.x; aA.y += wa * va.y; aA.z += wa * va.z; aA.w += wa * va.w;
        aB.x += wb * vb.x; aB.y += wb * vb.y; aB.z += wb * vb.z; aB.w += wb * vb.w;
    }
    float inv = 1.f / fmaxf((float)(e - s), 1.f);
    aA.x *= inv; aA.y *= inv; aA.z *= inv; aA.w *= inv;
    aB.x *= inv; aB.y *= inv; aB.z *= inv; aB.w *= inv;
    reinterpret_cast<float4*>(aggA)[(size_t)n * 32 + lane] = aA;
    reinterpret_cast<float4*>(aggB)[(size_t)n * 32 + lane] = aB;
}

// Cout[64-row tile,128] = maybe_relu(A @ W + D + bias), f32x2 packed FMA.
// 256 threads: tx = col-group (4 cols), ty = row-group (8 rows). Optional fused
// row-norm output (for x3).
__global__ __launch_bounds__(256, 2)
void gemm128_kernel(const float* __restrict__ A, const float* __restrict__ W,
                    const float* __restrict__ D, const float* __restrict__ bias,
                    float* __restrict__ Cout, int nrows, int relu,
                    float* __restrict__ nrmOut) {
    extern __shared__ float sm[];
    float* Ws = sm;            // 128*128 floats
    float* As = sm + 16384;    // 64*128 floats
    int t = threadIdx.x;
    int tx = t & 31, ty = t >> 5;
    const float4* W4 = reinterpret_cast<const float4*>(W);
    float4* Ws4 = reinterpret_cast<float4*>(Ws);
    #pragma unroll
    for (int i = t; i < 4096; i += 256) Ws4[i] = W4[i];
    int row0 = blockIdx.x * 64;
    float4* As4 = reinterpret_cast<float4*>(As);
    #pragma unroll
    for (int i = t; i < 2048; i += 256) {
        int r = i >> 5, c = i & 31;
        int rr = row0 + r;
        As4[i] = (rr < nrows) ? reinterpret_cast<const float4*>(A)[(size_t)rr * 32 + c]
                              : make_float4(0.f, 0.f, 0.f, 0.f);
    }
    __syncthreads();

    unsigned long long acc[8][2];
    #pragma unroll
    for (int j = 0; j < 8; j++) { acc[j][0] = 0ull; acc[j][1] = 0ull; }
    const float* Asrow = As + (ty * 8) * Cc;

    for (int k = 0; k < Cc; k += 4) {
        unsigned long long wp[4][2];
        #pragma unroll
        for (int kk = 0; kk < 4; kk++) {
            float4 wv = Ws4[(k + kk) * 32 + tx];
            PACK2(wp[kk][0], wv.x, wv.y);
            PACK2(wp[kk][1], wv.z, wv.w);
        }
        #pragma unroll
        for (int j = 0; j < 8; j++) {
            float4 av = *reinterpret_cast<const float4*>(Asrow + j * Cc + k);
            unsigned long long pa;
            PACKD(pa, av.x);
            FMA2(acc[j][0], pa, wp[0][0]); FMA2(acc[j][1], pa, wp[0][1]);
            PACKD(pa, av.y);
            FMA2(acc[j][0], pa, wp[1][0]); FMA2(acc[j][1], pa, wp[1][1]);
            PACKD(pa, av.z);
            FMA2(acc[j][0], pa, wp[2][0]); FMA2(acc[j][1], pa, wp[2][1]);
            PACKD(pa, av.w);
            FMA2(acc[j][0], pa, wp[3][0]); FMA2(acc[j][1], pa, wp[3][1]);
        }
    }

    float4 bv = make_float4(0.f, 0.f, 0.f, 0.f);
    if (bias) bv = reinterpret_cast<const float4*>(bias)[tx];
    #pragma unroll
    for (int j = 0; j < 8; j++) {
        int rr = row0 + ty * 8 + j;
        if (rr >= nrows) continue;
        float4 v;
        UNPK(v.x, v.y, acc[j][0]);
        UNPK(v.z, v.w, acc[j][1]);
        if (D) {
            float4 d4 = reinterpret_cast<const float4*>(D)[(size_t)rr * 32 + tx];
            v.x += d4.x; v.y += d4.y; v.z += d4.z; v.w += d4.w;
        }
        v.x += bv.x; v.y += bv.y; v.z += bv.z; v.w += bv.w;
        if (relu) {
            v.x = fmaxf(v.x, 0.f); v.y = fmaxf(v.y, 0.f);
            v.z = fmaxf(v.z, 0.f); v.w = fmaxf(v.w, 0.f);
        }
        reinterpret_cast<float4*>(Cout)[(size_t)rr * 32 + tx] = v;
        if (nrmOut) {
            float s = v.x * v.x + v.y * v.y + v.z * v.z + v.w * v.w;
            #pragma unroll
            for (int o = 16; o; o >>= 1) s += __shfl_xor_sync(0xffffffffu, s, o);
            if (tx == 0) nrmOut[rr] = sqrtf(s);
        }
    }
}

// fused attention scores + softmax + weighted sum. 256 threads = 2 nodes/iter.
// per node: 4 warps (one per branch), each thread handles 2 hidden units (f32x2).
__global__ void attn_emb_kernel(const float* __restrict__ x1, const float* __restrict__ x2,
                                const float* __restrict__ x3, const float* __restrict__ x4,
                                const float* __restrict__ W1, const float* __restrict__ b1,
                                const float* __restrict__ W2, float* __restrict__ out) {
    __shared__ float W1s[Cc * 64];    // [c][h] row-major, 32KB
    __shared__ float zs[2][4 * Cc];
    __shared__ float sb[2][4];
    int t = threadIdx.x;
    {
        float4* d = reinterpret_cast<float4*>(W1s);
        const float4* s4 = reinterpret_cast<const float4*>(W1);
        for (int i = t; i < Cc * 16; i += 256) d[i] = s4[i];
    }
    int half = t >> 7;            // node sub-index 0/1
    int idx  = t & 127;           // channel
    int warp = t >> 5;            // 0..7
    int k    = warp & 3;          // branch
    int h2   = t & 31;            // hidden pair index
    float w2a = W2[2 * h2], w2b = W2[2 * h2 + 1];
    float b1a = b1[2 * h2], b1b = b1[2 * h2 + 1];
    __syncthreads();

    for (int base = blockIdx.x * 2; base < Nn; base += gridDim.x * 2) {
        int n = base + half;      // Nn even, base even < Nn -> always valid
        size_t off = (size_t)n * Cc + idx;
        zs[half][0 * Cc + idx] = x1[off];
        zs[half][1 * Cc + idx] = x2[off];
        zs[half][2 * Cc + idx] = x3[off];
        zs[half][3 * Cc + idx] = x4[off];
        __syncthreads();

        unsigned long long acc;
        PACK2(acc, b1a, b1b);
        const float4* z4 = reinterpret_cast<const float4*>(&zs[half][k * Cc]);
        #pragma unroll 4
        for (int c0 = 0; c0 < 32; c0++) {
            float4 zv = z4[c0];
            unsigned long long pz, pw;
            const float2* wrow;
            wrow = reinterpret_cast<const float2*>(&W1s[(4 * c0 + 0) * 64]) + h2;
            PACKD(pz, zv.x); PACK2(pw, wrow->x, wrow->y); FMA2(acc, pz, pw);
            wrow = reinterpret_cast<const float2*>(&W1s[(4 * c0 + 1) * 64]) + h2;
            PACKD(pz, zv.y); PACK2(pw, wrow->x, wrow->y); FMA2(acc, pz, pw);
            wrow = reinterpret_cast<const float2*>(&W1s[(4 * c0 + 2) * 64]) + h2;
            PACKD(pz, zv.z); PACK2(pw, wrow->x, wrow->y); FMA2(acc, pz, pw);
            wrow = reinterpret_cast<const float2*>(&W1s[(4 * c0 + 3) * 64]) + h2;
            PACKD(pz, zv.w); PACK2(pw, wrow->x, wrow->y); FMA2(acc, pz, pw);
        }
        float a0, a1;
        UNPK(a0, a1, acc);
        float s = tanhf(a0) * w2a + tanhf(a1) * w2b;
        #pragma unroll
        for (int o = 16; o; o >>= 1) s += __shfl_xor_sync(0xffffffffu, s, o);
        if (h2 == 0) sb[half][k] = s;
        __syncthreads();

        float s0 = sb[half][0], s1 = sb[half][1], s2 = sb[half][2], s3 = sb[half][3];
        float m = fmaxf(fmaxf(s0, s1), fmaxf(s2, s3));
        float e0 = __expf(s0 - m), e1 = __expf(s1 - m);
        float e2 = __expf(s2 - m), e3 = __expf(s3 - m);
        float inv = 1.f / (e0 + e1 + e2 + e3);
        out[off] = (e0 * zs[half][idx] + e1 * zs[half][Cc + idx] +
                    e2 * zs[half][2 * Cc + idx] + e3 * zs[half][3 * Cc + idx]) * inv;
        __syncthreads();
    }
}

// ----------------------------- launcher --------------------------------------

extern "C" void kernel_launch(void* const* d_in, const int* in_sizes, int n_in,
                              void* d_out, int out_size) {
    const float* x    = (const float*)d_in[0];
    const int*   row  = (const int*)d_in[1];
    const int*   col  = (const int*)d_in[2];
    const float* Wl0  = (const float*)d_in[3];
    const float* bl0  = (const float*)d_in[4];
    const float* Wr0  = (const float*)d_in[5];
    const float* Wl1  = (const float*)d_in[6];
    const float* bl1  = (const float*)d_in[7];
    const float* Wr1  = (const float*)d_in[8];
    const float* aW1  = (const float*)d_in[9];
    const float* ab1  = (const float*)d_in[10];
    const float* aW2  = (const float*)d_in[11];

    float* out = (float*)d_out;
    float* emb = out;
    float* x3  = out + (size_t)Nn * Cc;
    float* x4  = out + (size_t)2 * Nn * Cc;

    int *p_cnt, *p_cursor, *p_rs, *p_ecol;
    float *p_nrm, *p_aggA, *p_aggB, *p_xW, *p_xW2, *p_x1, *p_x2;
    cudaGetSymbolAddress((void**)&p_cnt, g_cnt);
    cudaGetSymbolAddress((void**)&p_cursor, g_cursor);
    cudaGetSymbolAddress((void**)&p_rs, g_rowstart);
    cudaGetSymbolAddress((void**)&p_ecol, g_ecol);
    cudaGetSymbolAddress((void**)&p_nrm, g_nrm);
    cudaGetSymbolAddress((void**)&p_aggA, g_aggA);
    cudaGetSymbolAddress((void**)&p_aggB, g_aggB);
    cudaGetSymbolAddress((void**)&p_xW, g_xW);
    cudaGetSymbolAddress((void**)&p_xW2, g_xW2);
    cudaGetSymbolAddress((void**)&p_x1, g_x1);
    cudaGetSymbolAddress((void**)&p_x2, g_x2);

    const int gemm_smem = (Cc * Cc + 64 * Cc) * (int)sizeof(float);  // 98304
    cudaFuncSetAttribute(gemm128_kernel, cudaFuncAttributeMaxDynamicSharedMemorySize, gemm_smem);

    const int warp_node_blocks = (Nn * 32 + 255) / 256;  // 6250
    const int edge_blocks      = (Ee + 255) / 256;       // 3125
    const int gemm_blocks      = (Nn + 63) / 64;         // 782

    // ---- CSR build ----
    zero_int_kernel<<<(Nn + 255) / 256, 256>>>(p_cnt, Nn);
    node_norm_kernel<<<warp_node_blocks, 256>>>(x, p_nrm);
    count_kernel<<<edge_blocks, 256>>>(row, p_cnt);
    scan_kernel<<<1, 1024>>>(p_cnt, p_rs, p_cursor);
    fill_kernel<<<edge_blocks, 256>>>(row, col, p_cursor, p_ecol);

    // ---- layer 0 (similarity fused into gather) ----
    gather_fused0_kernel<<<warp_node_blocks, 256>>>(p_rs, p_ecol, x, p_nrm, p_aggA, p_aggB);
    gemm128_kernel<<<gemm_blocks, 256, gemm_smem>>>(x, Wr0, nullptr, nullptr, p_xW, Nn, 0, nullptr);
    gemm128_kernel<<<gemm_blocks, 256, gemm_smem>>>(p_aggA, Wl0, p_xW, bl0, x3, Nn, 1, p_nrm);
    gemm128_kernel<<<gemm_blocks, 256, gemm_smem>>>(p_aggB, Wl0, p_xW, bl0, x4, Nn, 1, nullptr);

    // ---- layer 1 (similarity fused into gather) ----
    gather_fused1_kernel<<<warp_node_blocks, 256>>>(p_rs, p_ecol, x3, x4, p_nrm, p_aggA, p_aggB);
    gemm128_kernel<<<gemm_blocks, 256, gemm_smem>>>(x3, Wr1, nullptr, nullptr, p_xW, Nn, 0, nullptr);
    gemm128_kernel<<<gemm_blocks, 256, gemm_smem>>>(x4, Wr1, nullptr, nullptr, p_xW2, Nn, 0, nullptr);
    gemm128_kernel<<<gemm_blocks, 256, gemm_smem>>>(p_aggA, Wl1, p_xW, bl1, p_x1, Nn, 0, nullptr);
    gemm128_kernel<<<gemm_blocks, 256, gemm_smem>>>(p_aggB, Wl1, p_xW2, bl1, p_x2, Nn, 0, nullptr);

    // ---- attention pooling + emb (fused) ----
    attn_emb_kernel<<<1480, 256>>>(p_x1, p_x2, x3, x4, aW1, ab1, aW2, emb);
}

// round 14
// speedup vs baseline: 2.6341x; 1.0170x over previous
#include <cuda_runtime.h>
#include <cuda_bf16.h>
#include <math.h>

#define Nn 50000
#define Ee 800000
#define Cc 128
#define EPS_COS 1e-8f
#define EPS_EUD 1e-6f

// ---------------- f32x2 packed-math macros (ptxas won't auto-fuse) ----------
#define PACKD(d, a)   asm("mov.b64 %0, {%1, %1};" : "=l"(d) : "r"(__float_as_int(a)))
#define PACK2(d, a, b) asm("mov.b64 %0, {%1, %2};" : "=l"(d) : "r"(__float_as_int(a)), "r"(__float_as_int(b)))
#define FMA2(acc, a, b) asm("fma.rn.f32x2 %0, %1, %2, %0;" : "+l"(acc) : "l"(a), "l"(b))
#define UNPK(lo, hi, v) do { unsigned int _u0, _u1; \
    asm("mov.b64 {%0, %1}, %2;" : "=r"(_u0), "=r"(_u1) : "l"(v)); \
    lo = __int_as_float(_u0); hi = __int_as_float(_u1); } while (0)

// ------------------- scratch (device globals; no allocs allowed) -------------
#define SCAN_BLOCKS 49
__device__ int   g_cnt[Nn];
__device__ int   g_cursor[Nn];
__device__ int   g_rowstart[Nn + 1];
__device__ int   g_partial[SCAN_BLOCKS];
__device__ int   g_ecol[Ee];
__device__ float g_nrm[Nn];
__device__ float g_aggA[Nn * Cc];
__device__ float g_aggB[Nn * Cc];
__device__ float g_x1[Nn * Cc];
__device__ float g_x2[Nn * Cc];

// ----------------------------- kernels --------------------------------------

__global__ void zero_int_kernel(int* __restrict__ p, int n) {
    int i = blockIdx.x * blockDim.x + threadIdx.x;
    if (i < n) p[i] = 0;
}

// one warp per node: L2 norm of each 128-float row (input x only)
__global__ void node_norm_kernel(const float* __restrict__ x, float* __restrict__ nrm) {
    int node = (blockIdx.x * blockDim.x + threadIdx.x) >> 5;
    int lane = threadIdx.x & 31;
    if (node >= Nn) return;
    float4 v = reinterpret_cast<const float4*>(x + (size_t)node * Cc)[lane];
    float s = v.x * v.x + v.y * v.y + v.z * v.z + v.w * v.w;
    #pragma unroll
    for (int o = 16; o; o >>= 1) s += __shfl_xor_sync(0xffffffffu, s, o);
    if (lane == 0) nrm[node] = sqrtf(s);
}

__global__ void count_kernel(const int* __restrict__ row, int* __restrict__ cnt) {
    int e = blockIdx.x * blockDim.x + threadIdx.x;
    if (e < Ee) atomicAdd(&cnt[row[e]], 1);
}

// ---- parallel scan: per-block sums -> tiny offset scan -> final scan ----
__global__ void scan_partial_kernel(const int* __restrict__ cnt, int* __restrict__ partial) {
    __shared__ int ws[32];
    int t = threadIdx.x, lane = t & 31, w = t >> 5;
    int i = blockIdx.x * 1024 + t;
    int v = (i < Nn) ? cnt[i] : 0;
    #pragma unroll
    for (int o = 16; o; o >>= 1) v += __shfl_xor_sync(0xffffffffu, v, o);
    if (lane == 0) ws[w] = v;
    __syncthreads();
    if (w == 0) {
        int s = ws[lane];
        #pragma unroll
        for (int o = 16; o; o >>= 1) s += __shfl_xor_sync(0xffffffffu, s, o);
        if (lane == 0) partial[blockIdx.x] = s;
    }
}

__global__ void scan_offsets_kernel(int* __restrict__ partial, int* __restrict__ row_start) {
    if (threadIdx.x == 0) {
        int run = 0;
        for (int i = 0; i < SCAN_BLOCKS; i++) { int t = partial[i]; partial[i] = run; run += t; }
        row_start[Nn] = run;
    }
}

__global__ void scan_final_kernel(const int* __restrict__ cnt, const int* __restrict__ partial,
                                  int* __restrict__ row_start, int* __restrict__ cursor) {
    __shared__ int wsum[32];
    int t = threadIdx.x, lane = t & 31, w = t >> 5;
    int i = blockIdx.x * 1024 + t;
    int v = (i < Nn) ? cnt[i] : 0;
    int xx = v;
    #pragma unroll
    for (int o = 1; o < 32; o <<= 1) {
        int y = __shfl_up_sync(0xffffffffu, xx, o);
        if (lane >= o) xx += y;
    }
    if (lane == 31) wsum[w] = xx;
    __syncthreads();
    if (w == 0) {
        int s = wsum[lane];
        #pragma unroll
        for (int o = 1; o < 32; o <<= 1) {
            int y = __shfl_up_sync(0xffffffffu, s, o);
            if (lane >= o) s += y;
        }
        wsum[lane] = s;
    }
    __syncthreads();
    int excl = partial[blockIdx.x] + (w ? wsum[w - 1] : 0) + xx - v;
    if (i < Nn) { row_start[i] = excl; cursor[i] = excl; }
}

// thread per edge: CSR column fill only (weights computed inline in gathers)
__global__ void fill_kernel(const int* __restrict__ row, const int* __restrict__ col,
                            int* __restrict__ cursor, int* __restrict__ ecol) {
    int e = blockIdx.x * blockDim.x + threadIdx.x;
    if (e >= Ee) return;
    int r = __ldg(row + e);
    int pos = atomicAdd(&cursor[r], 1);
    ecol[pos] = __ldg(col + e);
}

// warp per node, layer 0: inline cos+eud weights from x, dual accumulate.
__global__ void gather_fused0_kernel(const int* __restrict__ rs, const int* __restrict__ ecol,
                                     const float* __restrict__ x, const float* __restrict__ nrm,
                                     float* __restrict__ aggA, float* __restrict__ aggB) {
    int n = (blockIdx.x * blockDim.x + threadIdx.x) >> 5;
    int lane = threadIdx.x & 31;
    if (n >= Nn) return;
    int s = rs[n], e = rs[n + 1];
    float4 xn = reinterpret_cast<const float4*>(x)[(size_t)n * 32 + lane];
    float nn = nrm[n];
    float4 aA = make_float4(0.f, 0.f, 0.f, 0.f);
    float4 aB = make_float4(0.f, 0.f, 0.f, 0.f);
    #pragma unroll 2
    for (int j = s; j < e; j++) {
        int c = __ldg(ecol + j);
        float4 v = reinterpret_cast<const float4*>(x)[(size_t)c * 32 + lane];
        float dot = xn.x * v.x + xn.y * v.y + xn.z * v.z + xn.w * v.w;
        float dx = xn.x - v.x + EPS_EUD, dy = xn.y - v.y + EPS_EUD;
        float dz = xn.z - v.z + EPS_EUD, dw = xn.w - v.w + EPS_EUD;
        float d2 = dx * dx + dy * dy + dz * dz + dw * dw;
        #pragma unroll
        for (int o = 16; o; o >>= 1) {
            dot += __shfl_xor_sync(0xffffffffu, dot, o);
            d2  += __shfl_xor_sync(0xffffffffu, d2, o);
        }
        float wa = dot / fmaxf(nn * __ldg(nrm + c), EPS_COS);
        float wb = sqrtf(d2);
        aA.x += wa * v.x; aA.y += wa * v.y; aA.z += wa * v.z; aA.w += wa * v.w;
        aB.x += wb * v.x; aB.y += wb * v.y; aB.z += wb * v.z; aB.w += wb * v.w;
    }
    float inv = 1.f / fmaxf((float)(e - s), 1.f);
    aA.x *= inv; aA.y *= inv; aA.z *= inv; aA.w *= inv;
    aB.x *= inv; aB.y *= inv; aB.z *= inv; aB.w *= inv;
    reinterpret_cast<float4*>(aggA)[(size_t)n * 32 + lane] = aA;
    reinterpret_cast<float4*>(aggB)[(size_t)n * 32 + lane] = aB;
}

// warp per node, layer 1: cos on x3 (-> aggA from x3), eud on x4 (-> aggB from x4).
__global__ void gather_fused1_kernel(const int* __restrict__ rs, const int* __restrict__ ecol,
                                     const float* __restrict__ x3, const float* __restrict__ x4,
                                     const float* __restrict__ nrm3,
                                     float* __restrict__ aggA, float* __restrict__ aggB) {
    int n = (blockIdx.x * blockDim.x + threadIdx.x) >> 5;
    int lane = threadIdx.x & 31;
    if (n >= Nn) return;
    int s = rs[n], e = rs[n + 1];
    float4 an = reinterpret_cast<const float4*>(x3)[(size_t)n * 32 + lane];
    float4 bn = reinterpret_cast<const float4*>(x4)[(size_t)n * 32 + lane];
    float nn = nrm3[n];
    float4 aA = make_float4(0.f, 0.f, 0.f, 0.f);
    float4 aB = make_float4(0.f, 0.f, 0.f, 0.f);
    #pragma unroll 2
    for (int j = s; j < e; j++) {
        int c = __ldg(ecol + j);
        float4 va = reinterpret_cast<const float4*>(x3)[(size_t)c * 32 + lane];
        float4 vb = reinterpret_cast<const float4*>(x4)[(size_t)c * 32 + lane];
        float dot = an.x * va.x + an.y * va.y + an.z * va.z + an.w * va.w;
        float dx = bn.x - vb.x + EPS_EUD, dy = bn.y - vb.y + EPS_EUD;
        float dz = bn.z - vb.z + EPS_EUD, dw = bn.w - vb.w + EPS_EUD;
        float d2 = dx * dx + dy * dy + dz * dz + dw * dw;
        #pragma unroll
        for (int o = 16; o; o >>= 1) {
            dot += __shfl_xor_sync(0xffffffffu, dot, o);
            d2  += __shfl_xor_sync(0xffffffffu, d2, o);
        }
        float wa = dot / fmaxf(nn * __ldg(nrm3 + c), EPS_COS);
        float wb = sqrtf(d2);
        aA.x += wa * va.x; aA.y += wa * va.y; aA.z += wa * va.z; aA.w += wa * va.w;
        aB.x += wb * vb.x; aB.y += wb * vb.y; aB.z += wb * vb.z; aB.w += wb * vb.w;
    }
    float inv = 1.f / fmaxf((float)(e - s), 1.f);
    aA.x *= inv; aA.y *= inv; aA.z *= inv; aA.w *= inv;
    aB.x *= inv; aB.y *= inv; aB.z *= inv; aB.w *= inv;
    reinterpret_cast<float4*>(aggA)[(size_t)n * 32 + lane] = aA;
    reinterpret_cast<float4*>(aggB)[(size_t)n * 32 + lane] = aB;
}

// ---- shared GEMM tile machinery ----
__device__ __forceinline__ void load_W(float* Ws, const float* __restrict__ W, int t) {
    const float4* W4 = reinterpret_cast<const float4*>(W);
    float4* Ws4 = reinterpret_cast<float4*>(Ws);
    #pragma unroll
    for (int i = t; i < 4096; i += 256) Ws4[i] = W4[i];
}

__device__ __forceinline__ void load_A(float* As, const float* __restrict__ A, int row0, int t) {
    float4* As4 = reinterpret_cast<float4*>(As);
    #pragma unroll
    for (int i = t; i < 2048; i += 256) {
        int r = i >> 5, c = i & 31;
        int rr = row0 + r;
        As4[i] = (rr < Nn) ? reinterpret_cast<const float4*>(A)[(size_t)rr * 32 + c]
                           : make_float4(0.f, 0.f, 0.f, 0.f);
    }
}

// acc += As_tile(8 rows at ty) @ Ws (128x128), f32x2 packed
__device__ __forceinline__ void mma_tile(const float* As, const float* Ws,
                                         unsigned long long acc[8][2], int tx, int ty) {
    const float4* Ws4 = reinterpret_cast<const float4*>(Ws);
    const float* Asrow = As + (ty * 8) * Cc;
    for (int k = 0; k < Cc; k += 4) {
        unsigned long long wp[4][2];
        #pragma unroll
        for (int kk = 0; kk < 4; kk++) {
            float4 wv = Ws4[(k + kk) * 32 + tx];
            PACK2(wp[kk][0], wv.x, wv.y);
            PACK2(wp[kk][1], wv.z, wv.w);
        }
        #pragma unroll
        for (int j = 0; j < 8; j++) {
            float4 av = *reinterpret_cast<const float4*>(Asrow + j * Cc + k);
            unsigned long long pa;
            PACKD(pa, av.x);
            FMA2(acc[j][0], pa, wp[0][0]); FMA2(acc[j][1], pa, wp[0][1]);
            PACKD(pa, av.y);
            FMA2(acc[j][0], pa, wp[1][0]); FMA2(acc[j][1], pa, wp[1][1]);
            PACKD(pa, av.z);
            FMA2(acc[j][0], pa, wp[2][0]); FMA2(acc[j][1], pa, wp[2][1]);
            PACKD(pa, av.w);
            FMA2(acc[j][0], pa, wp[3][0]); FMA2(acc[j][1], pa, wp[3][1]);
        }
    }
}

__device__ __forceinline__ void epilogue(unsigned long long acc[8][2], const float* __restrict__ bias,
                                         float* __restrict__ Cout, int row0, int tx, int ty,
                                         int relu, float* __restrict__ nrmOut) {
    float4 bv = reinterpret_cast<const float4*>(bias)[tx];
    #pragma unroll
    for (int j = 0; j < 8; j++) {
        int rr = row0 + ty * 8 + j;
        if (rr >= Nn) continue;
        float4 v;
        UNPK(v.x, v.y, acc[j][0]);
        UNPK(v.z, v.w, acc[j][1]);
        v.x += bv.x; v.y += bv.y; v.z += bv.z; v.w += bv.w;
        if (relu) {
            v.x = fmaxf(v.x, 0.f); v.y = fmaxf(v.y, 0.f);
            v.z = fmaxf(v.z, 0.f); v.w = fmaxf(v.w, 0.f);
        }
        reinterpret_cast<float4*>(Cout)[(size_t)rr * 32 + tx] = v;
        if (nrmOut) {
            float s = v.x * v.x + v.y * v.y + v.z * v.z + v.w * v.w;
            #pragma unroll
            for (int o = 16; o; o >>= 1) s += __shfl_xor_sync(0xffffffffu, s, o);
            if (tx == 0) nrmOut[rr] = sqrtf(s);
        }
    }
}

// Multi-phase fused SAGE GEMM over a 64-row tile:
//   T = A1 @ W1      (kept in registers; the shared x@Wr term)
//   out1 = act(A2 @ W2 + T + bias)   [+ optional row norms]
//   out2 = act(A3 @ W2 + T + bias)   [optional third phase, W2 stays in smem]
__global__ __launch_bounds__(256)
void gemm_fused_kernel(const float* __restrict__ A1, const float* __restrict__ W1,
                       const float* __restrict__ A2, const float* __restrict__ W2,
                       const float* __restrict__ bias,
                       float* __restrict__ out1, int relu, float* __restrict__ nrmOut,
                       const float* __restrict__ A3, float* __restrict__ out2) {
    extern __shared__ float sm[];
    float* Ws = sm;            // 128*128 floats
    float* As = sm + 16384;    // 64*128 floats
    int t = threadIdx.x;
    int tx = t & 31, ty = t >> 5;
    int row0 = blockIdx.x * 64;

    // phase 1: T = A1 @ W1
    load_W(Ws, W1, t);
    load_A(As, A1, row0, t);
    __syncthreads();
    unsigned long long T[8][2];
    #pragma unroll
    for (int j = 0; j < 8; j++) { T[j][0] = 0ull; T[j][1] = 0ull; }
    mma_tile(As, Ws, T, tx, ty);
    __syncthreads();

    // phase 2: out1 = act(A2 @ W2 + T + bias)
    load_W(Ws, W2, t);
    load_A(As, A2, row0, t);
    __syncthreads();
    unsigned long long acc[8][2];
    #pragma unroll
    for (int j = 0; j < 8; j++) { acc[j][0] = T[j][0]; acc[j][1] = T[j][1]; }
    mma_tile(As, Ws, acc, tx, ty);
    epilogue(acc, bias, out1, row0, tx, ty, relu, nrmOut);

    // phase 3: out2 = act(A3 @ W2 + T + bias), reuse resident W2
    if (A3) {
        __syncthreads();
        load_A(As, A3, row0, t);
        __syncthreads();
        #pragma unroll
        for (int j = 0; j < 8; j++) { acc[j][0] = T[j][0]; acc[j][1] = T[j][1]; }
        mma_tile(As, Ws, acc, tx, ty);
        epilogue(acc, bias, out2, row0, tx, ty, relu, nullptr);
    }
}

// fused attention scores + softmax + weighted sum. 256 threads = 2 nodes/iter.
__global__ void attn_emb_kernel(const float* __restrict__ x1, const float* __restrict__ x2,
                                const float* __restrict__ x3, const float* __restrict__ x4,
                                const float* __restrict__ W1, const float* __restrict__ b1,
                                const float* __restrict__ W2, float* __restrict__ out) {
    __shared__ float W1s[Cc * 64];    // [c][h] row-major, 32KB
    __shared__ float zs[2][4 * Cc];
    __shared__ float sb[2][4];
    int t = threadIdx.x;
    {
        float4* d = reinterpret_cast<float4*>(W1s);
        const float4* s4 = reinterpret_cast<const float4*>(W1);
        for (int i = t; i < Cc * 16; i += 256) d[i] = s4[i];
    }
    int half = t >> 7;            // node sub-index 0/1
    int idx  = t & 127;           // channel
    int warp = t >> 5;            // 0..7
    int k    = warp & 3;          // branch
    int h2   = t & 31;            // hidden pair index
    float w2a = W2[2 * h2], w2b = W2[2 * h2 + 1];
    float b1a = b1[2 * h2], b1b = b1[2 * h2 + 1];
    __syncthreads();

    for (int base = blockIdx.x * 2; base < Nn; base += gridDim.x * 2) {
        int n = base + half;      // Nn even -> always valid
        size_t off = (size_t)n * Cc + idx;
        zs[half][0 * Cc + idx] = x1[off];
        zs[half][1 * Cc + idx] = x2[off];
        zs[half][2 * Cc + idx] = x3[off];
        zs[half][3 * Cc + idx] = x4[off];
        __syncthreads();

        unsigned long long acc;
        PACK2(acc, b1a, b1b);
        const float4* z4 = reinterpret_cast<const float4*>(&zs[half][k * Cc]);
        #pragma unroll 4
        for (int c0 = 0; c0 < 32; c0++) {
            float4 zv = z4[c0];
            unsigned long long pz, pw;
            const float2* wrow;
            wrow = reinterpret_cast<const float2*>(&W1s[(4 * c0 + 0) * 64]) + h2;
            PACKD(pz, zv.x); PACK2(pw, wrow->x, wrow->y); FMA2(acc, pz, pw);
            wrow = reinterpret_cast<const float2*>(&W1s[(4 * c0 + 1) * 64]) + h2;
            PACKD(pz, zv.y); PACK2(pw, wrow->x, wrow->y); FMA2(acc, pz, pw);
            wrow = reinterpret_cast<const float2*>(&W1s[(4 * c0 + 2) * 64]) + h2;
            PACKD(pz, zv.z); PACK2(pw, wrow->x, wrow->y); FMA2(acc, pz, pw);
            wrow = reinterpret_cast<const float2*>(&W1s[(4 * c0 + 3) * 64]) + h2;
            PACKD(pz, zv.w); PACK2(pw, wrow->x, wrow->y); FMA2(acc, pz, pw);
        }
        float a0, a1;
        UNPK(a0, a1, acc);
        float s = tanhf(a0) * w2a + tanhf(a1) * w2b;
        #pragma unroll
        for (int o = 16; o; o >>= 1) s += __shfl_xor_sync(0xffffffffu, s, o);
        if (h2 == 0) sb[half][k] = s;
        __syncthreads();

        float s0 = sb[half][0], s1 = sb[half][1], s2 = sb[half][2], s3 = sb[half][3];
        float m = fmaxf(fmaxf(s0, s1), fmaxf(s2, s3));
        float e0 = __expf(s0 - m), e1 = __expf(s1 - m);
        float e2 = __expf(s2 - m), e3 = __expf(s3 - m);
        float inv = 1.f / (e0 + e1 + e2 + e3);
        out[off] = (e0 * zs[half][idx] + e1 * zs[half][Cc + idx] +
                    e2 * zs[half][2 * Cc + idx] + e3 * zs[half][3 * Cc + idx]) * inv;
        __syncthreads();
    }
}

// ----------------------------- launcher --------------------------------------

extern "C" void kernel_launch(void* const* d_in, const int* in_sizes, int n_in,
                              void* d_out, int out_size) {
    const float* x    = (const float*)d_in[0];
    const int*   row  = (const int*)d_in[1];
    const int*   col  = (const int*)d_in[2];
    const float* Wl0  = (const float*)d_in[3];
    const float* bl0  = (const float*)d_in[4];
    const float* Wr0  = (const float*)d_in[5];
    const float* Wl1  = (const float*)d_in[6];
    const float* bl1  = (const float*)d_in[7];
    const float* Wr1  = (const float*)d_in[8];
    const float* aW1  = (const float*)d_in[9];
    const float* ab1  = (const float*)d_in[10];
    const float* aW2  = (const float*)d_in[11];

    float* out = (float*)d_out;
    float* emb = out;
    float* x3  = out + (size_t)Nn * Cc;
    float* x4  = out + (size_t)2 * Nn * Cc;

    int *p_cnt, *p_cursor, *p_rs, *p_partial, *p_ecol;
    float *p_nrm, *p_aggA, *p_aggB, *p_x1, *p_x2;
    cudaGetSymbolAddress((void**)&p_cnt, g_cnt);
    cudaGetSymbolAddress((void**)&p_cursor, g_cursor);
    cudaGetSymbolAddress((void**)&p_rs, g_rowstart);
    cudaGetSymbolAddress((void**)&p_partial, g_partial);
    cudaGetSymbolAddress((void**)&p_ecol, g_ecol);
    cudaGetSymbolAddress((void**)&p_nrm, g_nrm);
    cudaGetSymbolAddress((void**)&p_aggA, g_aggA);
    cudaGetSymbolAddress((void**)&p_aggB, g_aggB);
    cudaGetSymbolAddress((void**)&p_x1, g_x1);
    cudaGetSymbolAddress((void**)&p_x2, g_x2);

    const int gemm_smem = (Cc * Cc + 64 * Cc) * (int)sizeof(float);  // 98304
    cudaFuncSetAttribute(gemm_fused_kernel, cudaFuncAttributeMaxDynamicSharedMemorySize, gemm_smem);

    const int warp_node_blocks = (Nn * 32 + 255) / 256;  // 6250
    const int edge_blocks      = (Ee + 255) / 256;       // 3125
    const int gemm_blocks      = (Nn + 63) / 64;         // 782

    // ---- CSR build (parallel scan) ----
    zero_int_kernel<<<(Nn + 255) / 256, 256>>>(p_cnt, Nn);
    node_norm_kernel<<<warp_node_blocks, 256>>>(x, p_nrm);
    count_kernel<<<edge_blocks, 256>>>(row, p_cnt);
    scan_partial_kernel<<<SCAN_BLOCKS, 1024>>>(p_cnt, p_partial);
    scan_offsets_kernel<<<1, 32>>>(p_partial, p_rs);
    scan_final_kernel<<<SCAN_BLOCKS, 1024>>>(p_cnt, p_partial, p_rs, p_cursor);
    fill_kernel<<<edge_blocks, 256>>>(row, col, p_cursor, p_ecol);

    // ---- layer 0: gather + fused triple GEMM (x@Wr0 shared in registers) ----
    gather_fused0_kernel<<<warp_node_blocks, 256>>>(p_rs, p_ecol, x, p_nrm, p_aggA, p_aggB);
    gemm_fused_kernel<<<gemm_blocks, 256, gemm_smem>>>(
        x, Wr0, p_aggA, Wl0, bl0, x3, 1, p_nrm, p_aggB, x4);

    // ---- layer 1: gather + two fused dual GEMMs (no xW round-trips) ----
    gather_fused1_kernel<<<warp_node_blocks, 256>>>(p_rs, p_ecol, x3, x4, p_nrm, p_aggA, p_aggB);
    gemm_fused_kernel<<<gemm_blocks, 256, gemm_smem>>>(
        x3, Wr1, p_aggA, Wl1, bl1, p_x1, 0, nullptr, nullptr, nullptr);
    gemm_fused_kernel<<<gemm_blocks, 256, gemm_smem>>>(
        x4, Wr1, p_aggB, Wl1, bl1, p_x2, 0, nullptr, nullptr, nullptr);

    // ---- attention pooling + emb (fused) ----
    attn_emb_kernel<<<1480, 256>>>(p_x1, p_x2, x3, x4, aW1, ab1, aW2, emb);
}